// round 13
// baseline (speedup 1.0000x reference)
#include <cuda_runtime.h>
#include <cuda_fp16.h>
#include <cuda_pipeline.h>
#include <cstdint>

#define T_TOK 512
#define H_DIM 4096
#define F_DIM 14336
#define KC 64
#define THREADS 512
#define M_TILE 256
#define SPLIT 7

// smem: A 3 stages x (256 x 128B), B 2 bufs x (128 x 128B)
#define SA_STAGE 32768
#define SB_OFF   (3 * SA_STAGE)          // 98304
#define SB_BUF   16384
#define SMEM_TOTAL (SB_OFF + 2 * SB_BUF) // 131072

// ---- scratch ----
__device__ __half g_Xh[(size_t)T_TOK * H_DIM];
__device__ __half g_ACT[(size_t)T_TOK * F_DIM];
__device__ float  g_P2[(size_t)SPLIT * T_TOK * H_DIM];

__device__ __forceinline__ uint32_t smem_to_u32(const void* p) {
    uint32_t a;
    asm("{ .reg .u64 t; cvta.to.shared.u64 t, %1; cvt.u32.u64 %0, t; }" : "=r"(a) : "l"(p));
    return a;
}
__device__ __forceinline__ void ldsm4(uint32_t* r, uint32_t addr) {
    asm volatile("ldmatrix.sync.aligned.m8n8.x4.shared.b16 {%0,%1,%2,%3}, [%4];"
                 : "=r"(r[0]), "=r"(r[1]), "=r"(r[2]), "=r"(r[3]) : "r"(addr));
}
__device__ __forceinline__ void mma16816(float* c, const uint32_t* a, const uint32_t* b) {
    asm volatile("mma.sync.aligned.m16n8k16.row.col.f32.f16.f16.f32 "
                 "{%0,%1,%2,%3}, {%4,%5,%6,%7}, {%8,%9}, {%0,%1,%2,%3};"
                 : "+f"(c[0]), "+f"(c[1]), "+f"(c[2]), "+f"(c[3])
                 : "r"(a[0]), "r"(a[1]), "r"(a[2]), "r"(a[3]), "r"(b[0]), "r"(b[1]));
}
__device__ __forceinline__ uint32_t h2u(__half2 h) { return *reinterpret_cast<uint32_t*>(&h); }

// ================= X fp32 -> fp16 =================
__global__ void convert_x_kernel(const float* __restrict__ x) {
    int i = blockIdx.x * blockDim.x + threadIdx.x;
    g_Xh[i] = __float2half(x[i]);
}

// ================= dequant-GEMM (mma.sync HMMA) =================
// MODE 0 (fused G1+G3): B rows 0-63 = W1 cols n0..n0+63, rows 64-127 = W3 same cols.
//   Warp wn owns output cols [n0+wn*16, +16): W1 frags from rows wn*16+, W3 frags
//   from rows 64+wn*16+ -> silu pairing stays intra-thread.
// MODE 1 (G2): B rows 0-127 = W2 cols n0..n0+127; partial fp32 -> outP + sp*T*H.
template<int MODE>
__global__ __launch_bounds__(THREADS, 1)
void tc_gemm(const __half* __restrict__ A,
             const int* __restrict__ Wqa, const int* __restrict__ Wqb,
             const float* __restrict__ sca, const float* __restrict__ zra,
             const float* __restrict__ scb, const float* __restrict__ zrb,
             int K_full, int NIT,
             __half* __restrict__ ACT, float* __restrict__ outP)
{
    extern __shared__ __align__(128) char smem[];
    const uint32_t sm = smem_to_u32(smem);
    const int tid = threadIdx.x;
    const int wid = tid >> 5, lane = tid & 31;
    const int wm = wid & 3, wn = wid >> 2;     // 4 M-warps x 4 N-warps
    int n0, m0, k_start, sp;
    if (MODE == 0) {
        m0 = blockIdx.x * M_TILE;              // gridDim.x = 2 (m fastest: L2 weight share)
        n0 = blockIdx.y * 64;                  // gridDim.y = 224
        k_start = 0; sp = 0;
    } else {
        int mt = blockIdx.x & 1; sp = blockIdx.x >> 1;   // gridDim.x = 14
        m0 = mt * M_TILE;
        n0 = blockIdx.y * 128;                 // gridDim.y = 32
        k_start = sp * (NIT * KC);
    }
    const int ksz = K_full >> 6;

    // ---- 2 dequant tasks per thread: B row brow (0..127), segment seg (8 ints) ----
    const int* wp[2]; const float* scp[2]; const float* zrp[2]; uint32_t sts[2];
    #pragma unroll
    for (int i = 0; i < 2; i++) {
        int t = i * THREADS + tid;
        int brow = t >> 3, seg = t & 7;
        const int* base = (MODE == 0 && i == 1) ? Wqb : Wqa;
        const float* sc_ = (MODE == 0 && i == 1) ? scb : sca;
        const float* zr_ = (MODE == 0 && i == 1) ? zrb : zra;
        int grow = n0 + ((MODE == 0) ? (brow & 63) : brow);
        wp[i]  = base + (size_t)grow * K_full + seg * 8;
        scp[i] = sc_ + (size_t)grow * ksz;
        zrp[i] = zr_ + (size_t)grow * ksz;
        sts[i] = SB_OFF + brow * 128 + ((seg * 16) ^ ((brow & 7) * 16));
    }
    int4 wq[2][2]; float scw[2], zrw[2];

#define LOADW(it_) do { int k0_ = k_start + (it_) * KC; int g_ = k0_ >> 6; \
    _Pragma("unroll") \
    for (int i_ = 0; i_ < 2; i_++) { \
        const int4* p_ = (const int4*)(wp[i_] + k0_); \
        wq[i_][0] = p_[0]; wq[i_][1] = p_[1]; \
        scw[i_] = scp[i_][g_]; zrw[i_] = zrp[i_][g_]; \
    } } while (0)

#define LOADA(it_, st_) do { int k0_ = k_start + (it_) * KC; \
    _Pragma("unroll") \
    for (int r_ = 0; r_ < 4; r_++) { \
        int idx_ = r_ * THREADS + tid; int row_ = idx_ >> 3, sg_ = idx_ & 7; \
        __pipeline_memcpy_async( \
            smem + (st_) * SA_STAGE + row_ * 128 + ((sg_ * 16) ^ ((row_ & 7) * 16)), \
            A + (size_t)(m0 + row_) * K_full + k0_ + sg_ * 8, 16); \
    } } while (0)

    // ---- ldmatrix addressing (swizzle applied per k-step) ----
    const int swz = (lane & 7) * 16;
    const int a_row = (lane & 7) + ((lane >> 3) & 1) * 8;
    const int a_c0 = (lane >> 4) * 16;
    uint32_t pA[4];
    #pragma unroll
    for (int i = 0; i < 4; i++)
        pA[i] = sm + (wm * 64 + i * 16 + a_row) * 128;
    const int b_n = (lane & 7) + (lane >> 4) * 8;
    const int b_c0 = ((lane >> 3) & 1) * 16;
    uint32_t pBr[2];
    if (MODE == 0) {
        pBr[0] = sm + SB_OFF + (wn * 16 + b_n) * 128;        // W1 frags
        pBr[1] = sm + SB_OFF + (64 + wn * 16 + b_n) * 128;   // W3 frags
    } else {
        pBr[0] = sm + SB_OFF + (wn * 32 + b_n) * 128;
        pBr[1] = sm + SB_OFF + (wn * 32 + 16 + b_n) * 128;
    }
    uint32_t akoff[4], bkoff[4];
    #pragma unroll
    for (int k = 0; k < 4; k++) {
        akoff[k] = (uint32_t)((a_c0 + k * 32) ^ swz);
        bkoff[k] = (uint32_t)((b_c0 + k * 32) ^ swz);
    }

    float acc[4][4][4];
    #pragma unroll
    for (int i = 0; i < 4; i++)
        #pragma unroll
        for (int j = 0; j < 4; j++)
            acc[i][j][0] = acc[i][j][1] = acc[i][j][2] = acc[i][j][3] = 0.0f;

    LOADW(0);
    LOADA(0, 0); __pipeline_commit();
    LOADA(1, 1); __pipeline_commit();
    int s_cur = 0, s_pre = 2;

    for (int it = 0; it < NIT; it++) {
        const int buf = it & 1;
        __pipeline_wait_prior(1);          // A[s_cur] complete

        // dequant 2 tasks -> swizzled fp16 B tile
        #pragma unroll
        for (int i = 0; i < 2; i++) {
            float nz = -zrw[i] * scw[i];
            __half2 v0 = __floats2half2_rn(fmaf((float)wq[i][0].x, scw[i], nz), fmaf((float)wq[i][0].y, scw[i], nz));
            __half2 v1 = __floats2half2_rn(fmaf((float)wq[i][0].z, scw[i], nz), fmaf((float)wq[i][0].w, scw[i], nz));
            __half2 v2 = __floats2half2_rn(fmaf((float)wq[i][1].x, scw[i], nz), fmaf((float)wq[i][1].y, scw[i], nz));
            __half2 v3 = __floats2half2_rn(fmaf((float)wq[i][1].z, scw[i], nz), fmaf((float)wq[i][1].w, scw[i], nz));
            uint4 v = { h2u(v0), h2u(v1), h2u(v2), h2u(v3) };
            *(uint4*)(smem + sts[i] + buf * SB_BUF) = v;
        }
        __syncthreads();                   // single barrier per chunk

        // prefetch next weights + A stage (latency hidden under compute)
        if (it + 1 < NIT) LOADW(it + 1);
        if (it + 2 < NIT) LOADA(it + 2, s_pre);
        __pipeline_commit();

        // compute: 4 k-steps x (4 M x 4 N) = 64 mma, 24 ldsm
        const uint32_t aoff = s_cur * SA_STAGE;
        const uint32_t boff = buf * SB_BUF;
        #pragma unroll
        for (int k = 0; k < 4; k++) {
            uint32_t bfr[2][4];
            ldsm4(bfr[0], pBr[0] + boff + bkoff[k]);
            ldsm4(bfr[1], pBr[1] + boff + bkoff[k]);
            uint32_t afr[2][4];
            ldsm4(afr[0], pA[0] + aoff + akoff[k]);
            #pragma unroll
            for (int i = 0; i < 4; i++) {
                if (i < 3) ldsm4(afr[(i + 1) & 1], pA[i + 1] + aoff + akoff[k]);
                #pragma unroll
                for (int j = 0; j < 4; j++)
                    mma16816(acc[i][j], afr[i & 1], bfr[j >> 1] + (j & 1) * 2);
            }
        }
        s_cur = (s_cur == 2) ? 0 : s_cur + 1;
        s_pre = (s_pre == 2) ? 0 : s_pre + 1;
    }

    // ---- epilogue ----
    const int r0 = m0 + wm * 64 + (lane >> 2);
    if constexpr (MODE == 0) {
        // acc[i][j] (j=0,1) = W1 outputs; acc[i][j+2] = W3 outputs, same cols
        #pragma unroll
        for (int i = 0; i < 4; i++) {
            #pragma unroll
            for (int j = 0; j < 2; j++) {
                int r = r0 + i * 16;
                int c = n0 + wn * 16 + j * 8 + (lane & 3) * 2;
                float h1a = acc[i][j][0], h1b = acc[i][j][1];
                float h1c = acc[i][j][2], h1d = acc[i][j][3];
                float o0 = h1a / (1.0f + __expf(-h1a)) * acc[i][j + 2][0];
                float o1 = h1b / (1.0f + __expf(-h1b)) * acc[i][j + 2][1];
                float o2 = h1c / (1.0f + __expf(-h1c)) * acc[i][j + 2][2];
                float o3 = h1d / (1.0f + __expf(-h1d)) * acc[i][j + 2][3];
                *(__half2*)(ACT + (size_t)r * F_DIM + c) = __floats2half2_rn(o0, o1);
                *(__half2*)(ACT + (size_t)(r + 8) * F_DIM + c) = __floats2half2_rn(o2, o3);
            }
        }
    } else {
        float* dst = outP + (size_t)sp * ((size_t)T_TOK * H_DIM);
        #pragma unroll
        for (int i = 0; i < 4; i++) {
            #pragma unroll
            for (int j = 0; j < 4; j++) {
                int r = r0 + i * 16;
                int c = n0 + wn * 32 + j * 8 + (lane & 3) * 2;
                float2 lo = { acc[i][j][0], acc[i][j][1] };
                float2 hi = { acc[i][j][2], acc[i][j][3] };
                *(float2*)(dst + (size_t)r * H_DIM + c) = lo;
                *(float2*)(dst + (size_t)(r + 8) * H_DIM + c) = hi;
            }
        }
    }
#undef LOADW
#undef LOADA
}

// ================= split-K reduce (7 partials) =================
__global__ void reduce7_kernel(float* __restrict__ out) {
    const size_t S = (size_t)T_TOK * H_DIM / 4;
    size_t i = (size_t)blockIdx.x * blockDim.x + threadIdx.x;
    const float4* p = (const float4*)g_P2;
    float4 r = p[i];
    #pragma unroll
    for (int s = 1; s < SPLIT; s++) {
        float4 v = p[i + (size_t)s * S];
        r.x += v.x; r.y += v.y; r.z += v.z; r.w += v.w;
    }
    ((float4*)out)[i] = r;
}

// ================= launch =================
extern "C" void kernel_launch(void* const* d_in, const int* in_sizes, int n_in,
                              void* d_out, int out_size) {
    const float* x  = (const float*)d_in[0];
    const int* W1q  = (const int*)d_in[1];
    const float* s1 = (const float*)d_in[2];
    const float* z1 = (const float*)d_in[3];
    const int* W3q  = (const int*)d_in[4];
    const float* s3 = (const float*)d_in[5];
    const float* z3 = (const float*)d_in[6];
    const int* W2q  = (const int*)d_in[7];
    const float* s2 = (const float*)d_in[8];
    const float* z2 = (const float*)d_in[9];
    float* out = (float*)d_out;

    void *pXh, *pACT, *pP2;
    cudaGetSymbolAddress(&pXh, g_Xh);
    cudaGetSymbolAddress(&pACT, g_ACT);
    cudaGetSymbolAddress(&pP2, g_P2);
    const __half* Xh = (const __half*)pXh;
    __half* ACT = (__half*)pACT;
    float* P2 = (float*)pP2;

    cudaFuncSetAttribute(tc_gemm<0>, cudaFuncAttributeMaxDynamicSharedMemorySize, SMEM_TOTAL);
    cudaFuncSetAttribute(tc_gemm<1>, cudaFuncAttributeMaxDynamicSharedMemorySize, SMEM_TOTAL);

    convert_x_kernel<<<(T_TOK * H_DIM) / 1024, 1024>>>(x);

    // fused G1+G3 -> ACT : grid (m fastest for L2 weight sharing)
    tc_gemm<0><<<dim3(T_TOK / M_TILE, F_DIM / 64), THREADS, SMEM_TOTAL>>>(
        Xh, W1q, W3q, s1, z1, s3, z3, H_DIM, H_DIM / KC, ACT, nullptr);

    // G2 split-K=7 : grid (14 = 2 m-tiles x 7 splits, 32 n-tiles)
    tc_gemm<1><<<dim3(2 * SPLIT, H_DIM / 128), THREADS, SMEM_TOTAL>>>(
        ACT, W2q, W2q, s2, z2, s2, z2, F_DIM, F_DIM / (KC * SPLIT), nullptr, P2);

    reduce7_kernel<<<(T_TOK * H_DIM / 4) / 256, 256>>>(out);
}

// round 14
// speedup vs baseline: 1.1450x; 1.1450x over previous
#include <cuda_runtime.h>
#include <cuda_fp16.h>
#include <cuda_pipeline.h>
#include <cstdint>

#define T_TOK 512
#define H_DIM 4096
#define F_DIM 14336
#define KC 64
#define THREADS 256
#define M_TILE 256
#define SPLIT 7

// smem: A 3 stages x (256 x 128B), B 2 bufs x (128 x 128B)
#define SA_STAGE 32768
#define SB_OFF   (3 * SA_STAGE)          // 98304
#define SB_BUF   16384
#define SMEM_TOTAL (SB_OFF + 2 * SB_BUF) // 131072

// ---- scratch ----
__device__ __half g_Xh[(size_t)T_TOK * H_DIM];
__device__ __half g_ACT[(size_t)T_TOK * F_DIM];
__device__ float  g_P2[(size_t)SPLIT * T_TOK * H_DIM];

__device__ __forceinline__ uint32_t smem_to_u32(const void* p) {
    uint32_t a;
    asm("{ .reg .u64 t; cvta.to.shared.u64 t, %1; cvt.u32.u64 %0, t; }" : "=r"(a) : "l"(p));
    return a;
}
__device__ __forceinline__ void ldsm4(uint32_t* r, uint32_t addr) {
    asm volatile("ldmatrix.sync.aligned.m8n8.x4.shared.b16 {%0,%1,%2,%3}, [%4];"
                 : "=r"(r[0]), "=r"(r[1]), "=r"(r[2]), "=r"(r[3]) : "r"(addr));
}
__device__ __forceinline__ void mma16816(float* c, const uint32_t* a, const uint32_t* b) {
    asm volatile("mma.sync.aligned.m16n8k16.row.col.f32.f16.f16.f32 "
                 "{%0,%1,%2,%3}, {%4,%5,%6,%7}, {%8,%9}, {%0,%1,%2,%3};"
                 : "+f"(c[0]), "+f"(c[1]), "+f"(c[2]), "+f"(c[3])
                 : "r"(a[0]), "r"(a[1]), "r"(a[2]), "r"(a[3]), "r"(b[0]), "r"(b[1]));
}
__device__ __forceinline__ uint32_t h2u(__half2 h) { return *reinterpret_cast<uint32_t*>(&h); }

// ================= X fp32 -> fp16 =================
__global__ void convert_x_kernel(const float* __restrict__ x) {
    int i = blockIdx.x * blockDim.x + threadIdx.x;
    g_Xh[i] = __float2half(x[i]);
}

// ================= dequant-GEMM (mma.sync HMMA) =================
// MODE 0 (fused G1+G3): B rows 0-63 = W1 cols n0..n0+63, rows 64-127 = W3 same cols.
//   epilogue: ACT = silu(X@W1^T) * (X@W3^T), fp16.
// MODE 1 (G2): B rows 0-127 = W2 cols n0..n0+127; partial fp32 -> outP + sp*T*H.
// B dequant for chunk it+1 is overlapped with compute of chunk it (writes buf^1).
template<int MODE>
__global__ __launch_bounds__(THREADS, 1)
void tc_gemm(const __half* __restrict__ A,
             const int* __restrict__ Wqa, const int* __restrict__ Wqb,
             const float* __restrict__ sca, const float* __restrict__ zra,
             const float* __restrict__ scb, const float* __restrict__ zrb,
             int K_full, int NIT,
             __half* __restrict__ ACT, float* __restrict__ outP)
{
    extern __shared__ __align__(128) char smem[];
    const uint32_t sm = smem_to_u32(smem);
    const int tid = threadIdx.x;
    const int wid = tid >> 5, lane = tid & 31;
    const int wm = wid & 3, wn = wid >> 2;     // 4 M-warps x 2 N-warps
    int n0, m0, k_start, sp;
    if (MODE == 0) {
        m0 = blockIdx.x * M_TILE;              // gridDim.x = 2 (m fastest: L2 weight share)
        n0 = blockIdx.y * 64;                  // gridDim.y = 224
        k_start = 0; sp = 0;
    } else {
        int mt = blockIdx.x & 1; sp = blockIdx.x >> 1;   // gridDim.x = 14
        m0 = mt * M_TILE;
        n0 = blockIdx.y * 128;                 // gridDim.y = 32
        k_start = sp * (NIT * KC);
    }
    const int ksz = K_full >> 6;

    // ---- 4 dequant tasks per thread: B row brow (0..127), segment seg (8 ints) ----
    const int* wp[4]; const float* scp[4]; const float* zrp[4]; uint32_t sts[4];
    #pragma unroll
    for (int i = 0; i < 4; i++) {
        int t = i * THREADS + tid;
        int brow = t >> 3, seg = t & 7;
        const int* base = (MODE == 0 && i >= 2) ? Wqb : Wqa;
        const float* sc_ = (MODE == 0 && i >= 2) ? scb : sca;
        const float* zr_ = (MODE == 0 && i >= 2) ? zrb : zra;
        int grow = n0 + ((MODE == 0) ? (brow & 63) : brow);
        wp[i]  = base + (size_t)grow * K_full + seg * 8;
        scp[i] = sc_ + (size_t)grow * ksz;
        zrp[i] = zr_ + (size_t)grow * ksz;
        sts[i] = SB_OFF + brow * 128 + ((seg * 16) ^ ((brow & 7) * 16));
    }
    int4 wq[4][2]; float scw[4], zrw[4];

#define LOADW(it_) do { int k0_ = k_start + (it_) * KC; int g_ = k0_ >> 6; \
    _Pragma("unroll") \
    for (int i_ = 0; i_ < 4; i_++) { \
        const int4* p_ = (const int4*)(wp[i_] + k0_); \
        wq[i_][0] = p_[0]; wq[i_][1] = p_[1]; \
        scw[i_] = scp[i_][g_]; zrw[i_] = zrp[i_][g_]; \
    } } while (0)

// dequant current wq regs -> swizzled fp16 B tile in buffer tb_
#define STSB(tb_) do { \
    _Pragma("unroll") \
    for (int i_ = 0; i_ < 4; i_++) { \
        float nz_ = -zrw[i_] * scw[i_]; \
        __half2 v0_ = __floats2half2_rn(fmaf((float)wq[i_][0].x, scw[i_], nz_), fmaf((float)wq[i_][0].y, scw[i_], nz_)); \
        __half2 v1_ = __floats2half2_rn(fmaf((float)wq[i_][0].z, scw[i_], nz_), fmaf((float)wq[i_][0].w, scw[i_], nz_)); \
        __half2 v2_ = __floats2half2_rn(fmaf((float)wq[i_][1].x, scw[i_], nz_), fmaf((float)wq[i_][1].y, scw[i_], nz_)); \
        __half2 v3_ = __floats2half2_rn(fmaf((float)wq[i_][1].z, scw[i_], nz_), fmaf((float)wq[i_][1].w, scw[i_], nz_)); \
        uint4 v_ = { h2u(v0_), h2u(v1_), h2u(v2_), h2u(v3_) }; \
        *(uint4*)(smem + sts[i_] + (tb_) * SB_BUF) = v_; \
    } } while (0)

#define LOADA(it_, st_) do { int k0_ = k_start + (it_) * KC; \
    _Pragma("unroll") \
    for (int r_ = 0; r_ < 8; r_++) { \
        int idx_ = r_ * THREADS + tid; int row_ = idx_ >> 3, sg_ = idx_ & 7; \
        __pipeline_memcpy_async( \
            smem + (st_) * SA_STAGE + row_ * 128 + ((sg_ * 16) ^ ((row_ & 7) * 16)), \
            A + (size_t)(m0 + row_) * K_full + k0_ + sg_ * 8, 16); \
    } } while (0)

    // ---- ldmatrix addressing (swizzle applied per k-step) ----
    const int swz = (lane & 7) * 16;
    const int a_row = (lane & 7) + ((lane >> 3) & 1) * 8;
    const int a_c0 = (lane >> 4) * 16;
    uint32_t pA[4];
    #pragma unroll
    for (int i = 0; i < 4; i++)
        pA[i] = sm + (wm * 64 + i * 16 + a_row) * 128;
    const int b_n = (lane & 7) + (lane >> 4) * 8;
    const int b_c0 = ((lane >> 3) & 1) * 16;
    uint32_t pBr[4];
    #pragma unroll
    for (int jj = 0; jj < 4; jj++) {
        int row = (MODE == 0) ? ((jj >> 1) * 64 + wn * 32 + (jj & 1) * 16 + b_n)
                              : (wn * 64 + jj * 16 + b_n);
        pBr[jj] = sm + SB_OFF + row * 128;
    }
    uint32_t akoff[4], bkoff[4];
    #pragma unroll
    for (int k = 0; k < 4; k++) {
        akoff[k] = (uint32_t)((a_c0 + k * 32) ^ swz);
        bkoff[k] = (uint32_t)((b_c0 + k * 32) ^ swz);
    }

    float acc[4][8][4];
    #pragma unroll
    for (int i = 0; i < 4; i++)
        #pragma unroll
        for (int j = 0; j < 8; j++)
            acc[i][j][0] = acc[i][j][1] = acc[i][j][2] = acc[i][j][3] = 0.0f;

    // ---- prologue: B(0) into buf0, weights(1) into regs, A stages 0/1 in flight ----
    LOADW(0);
    LOADA(0, 0); __pipeline_commit();
    LOADA(1, 1); __pipeline_commit();
    STSB(0);
    if (NIT > 1) LOADW(1);
    int s_cur = 0, s_pre = 2;
    __pipeline_wait_prior(1);              // A stage 0 complete
    __syncthreads();                       // B(0) visible to all warps

    for (int it = 0; it < NIT; it++) {
        const int buf = it & 1;

        // overlapped with compute: dequant B(it+1) -> buf^1, prefetch W(it+2), A(it+2)
        if (it + 1 < NIT) STSB(buf ^ 1);
        if (it + 2 < NIT) { LOADW(it + 2); LOADA(it + 2, s_pre); }
        __pipeline_commit();               // empty group ok on tail

        // compute: 4 k-steps x (4 M x 8 N) = 128 mma, 32 ldsm
        const uint32_t aoff = s_cur * SA_STAGE;
        const uint32_t boff = buf * SB_BUF;
        #pragma unroll
        for (int k = 0; k < 4; k++) {
            uint32_t bfr[4][4];
            #pragma unroll
            for (int jj = 0; jj < 4; jj++)
                ldsm4(bfr[jj], pBr[jj] + boff + bkoff[k]);
            uint32_t afr[2][4];
            ldsm4(afr[0], pA[0] + aoff + akoff[k]);
            #pragma unroll
            for (int i = 0; i < 4; i++) {
                if (i < 3) ldsm4(afr[(i + 1) & 1], pA[i + 1] + aoff + akoff[k]);
                #pragma unroll
                for (int j = 0; j < 8; j++)
                    mma16816(acc[i][j], afr[i & 1], bfr[j >> 1] + (j & 1) * 2);
            }
        }

        __pipeline_wait_prior(1);          // A stage (it+1) complete
        __syncthreads();                   // single barrier: B(it+1) visible, buf free
        s_cur = (s_cur == 2) ? 0 : s_cur + 1;
        s_pre = (s_pre == 2) ? 0 : s_pre + 1;
    }

    // ---- epilogue ----
    const int r0 = m0 + wm * 64 + (lane >> 2);
    if constexpr (MODE == 0) {
        #pragma unroll
        for (int i = 0; i < 4; i++) {
            #pragma unroll
            for (int j = 0; j < 4; j++) {
                int r = r0 + i * 16;
                int c = n0 + wn * 32 + j * 8 + (lane & 3) * 2;
                float h1a = acc[i][j][0], h1b = acc[i][j][1];
                float h1c = acc[i][j][2], h1d = acc[i][j][3];
                float o0 = h1a / (1.0f + __expf(-h1a)) * acc[i][j + 4][0];
                float o1 = h1b / (1.0f + __expf(-h1b)) * acc[i][j + 4][1];
                float o2 = h1c / (1.0f + __expf(-h1c)) * acc[i][j + 4][2];
                float o3 = h1d / (1.0f + __expf(-h1d)) * acc[i][j + 4][3];
                *(__half2*)(ACT + (size_t)r * F_DIM + c) = __floats2half2_rn(o0, o1);
                *(__half2*)(ACT + (size_t)(r + 8) * F_DIM + c) = __floats2half2_rn(o2, o3);
            }
        }
    } else {
        float* dst = outP + (size_t)sp * ((size_t)T_TOK * H_DIM);
        #pragma unroll
        for (int i = 0; i < 4; i++) {
            #pragma unroll
            for (int j = 0; j < 8; j++) {
                int r = r0 + i * 16;
                int c = n0 + wn * 64 + j * 8 + (lane & 3) * 2;
                float2 lo = { acc[i][j][0], acc[i][j][1] };
                float2 hi = { acc[i][j][2], acc[i][j][3] };
                *(float2*)(dst + (size_t)r * H_DIM + c) = lo;
                *(float2*)(dst + (size_t)(r + 8) * H_DIM + c) = hi;
            }
        }
    }
#undef LOADW
#undef STSB
#undef LOADA
}

// ================= split-K reduce (7 partials) =================
__global__ void reduce7_kernel(float* __restrict__ out) {
    const size_t S = (size_t)T_TOK * H_DIM / 4;
    size_t i = (size_t)blockIdx.x * blockDim.x + threadIdx.x;
    const float4* p = (const float4*)g_P2;
    float4 r = p[i];
    #pragma unroll
    for (int s = 1; s < SPLIT; s++) {
        float4 v = p[i + (size_t)s * S];
        r.x += v.x; r.y += v.y; r.z += v.z; r.w += v.w;
    }
    ((float4*)out)[i] = r;
}

// ================= launch =================
extern "C" void kernel_launch(void* const* d_in, const int* in_sizes, int n_in,
                              void* d_out, int out_size) {
    const float* x  = (const float*)d_in[0];
    const int* W1q  = (const int*)d_in[1];
    const float* s1 = (const float*)d_in[2];
    const float* z1 = (const float*)d_in[3];
    const int* W3q  = (const int*)d_in[4];
    const float* s3 = (const float*)d_in[5];
    const float* z3 = (const float*)d_in[6];
    const int* W2q  = (const int*)d_in[7];
    const float* s2 = (const float*)d_in[8];
    const float* z2 = (const float*)d_in[9];
    float* out = (float*)d_out;

    void *pXh, *pACT, *pP2;
    cudaGetSymbolAddress(&pXh, g_Xh);
    cudaGetSymbolAddress(&pACT, g_ACT);
    cudaGetSymbolAddress(&pP2, g_P2);
    const __half* Xh = (const __half*)pXh;
    __half* ACT = (__half*)pACT;
    float* P2 = (float*)pP2;

    cudaFuncSetAttribute(tc_gemm<0>, cudaFuncAttributeMaxDynamicSharedMemorySize, SMEM_TOTAL);
    cudaFuncSetAttribute(tc_gemm<1>, cudaFuncAttributeMaxDynamicSharedMemorySize, SMEM_TOTAL);

    convert_x_kernel<<<(T_TOK * H_DIM) / 1024, 1024>>>(x);

    // fused G1+G3 -> ACT : grid (m fastest for L2 weight sharing)
    tc_gemm<0><<<dim3(T_TOK / M_TILE, F_DIM / 64), THREADS, SMEM_TOTAL>>>(
        Xh, W1q, W3q, s1, z1, s3, z3, H_DIM, H_DIM / KC, ACT, nullptr);

    // G2 split-K=7 : grid (14 = 2 m-tiles x 7 splits, 32 n-tiles)
    tc_gemm<1><<<dim3(2 * SPLIT, H_DIM / 128), THREADS, SMEM_TOTAL>>>(
        ACT, W2q, W2q, s2, z2, s2, z2, F_DIM, F_DIM / (KC * SPLIT), nullptr, P2);

    reduce7_kernel<<<(T_TOK * H_DIM / 4) / 256, 256>>>(out);
}